// round 1
// baseline (speedup 1.0000x reference)
#include <cuda_runtime.h>
#include <cuda_bf16.h>
#include <math.h>

// Problem constants
#define BB   16
#define PP   4096
#define MM   1024
#define KK   16
#define FIN  64
#define FOUT 128
#define NN   (BB * PP)          // 65536
#define BN_EPS 1e-5f

#define OFF_P  (BB * MM * FOUT)            // 2097152
#define OFF_B  (OFF_P + BB * MM * 3)       // 2146304
#define TOTAL_OUT (OFF_B + BB * MM)        // 2162688

// -------- scratch (static device globals; no allocation allowed) --------
__device__ int   g_fps[BB * MM];
__device__ int   g_knn[BB * MM * KK];
__device__ float g_h[(size_t)NN * FOUT];        // 33.5 MB pre-BN activations
__device__ float g_psum[(NN / 32) * FOUT];      // 2048 x 128 partial sums
__device__ float g_psq [(NN / 32) * FOUT];
__device__ float g_mean[FOUT];
__device__ float g_var [FOUT];
__device__ float g_xx[NN];                      // per-point sum(x*x) in feature space

// ============================================================
// FPS: one block per cloud, 1024 threads, 4 points/thread.
// Exact match of JAX: d = ((dx*dx + dy*dy) + dz*dz) with no FMA,
// dist = min(dist, d), argmax = first max index.
// ============================================================
__global__ void fps_kernel(const float* __restrict__ pos)
{
    extern __shared__ float fsm[];
    float* sx = fsm;
    float* sy = fsm + PP;
    float* sz = fsm + 2 * PP;
    uint2* swp = (uint2*)(fsm + 3 * PP);   // 32 warp results
    __shared__ int s_last;

    const int b   = blockIdx.x;
    const int tid = threadIdx.x;
    const int lane = tid & 31;
    const int wid  = tid >> 5;

    const float* pb = pos + (size_t)b * PP * 3;
    for (int j = tid; j < PP; j += 1024) {
        sx[j] = pb[3 * j + 0];
        sy[j] = pb[3 * j + 1];
        sz[j] = pb[3 * j + 2];
    }
    __syncthreads();

    float x[4], y[4], z[4], dist[4];
#pragma unroll
    for (int s = 0; s < 4; s++) {
        int j = tid + s * 1024;
        x[s] = sx[j]; y[s] = sy[j]; z[s] = sz[j];
        dist[s] = INFINITY;
    }
    if (tid == 0) g_fps[b * MM] = 0;

    int last = 0;
    for (int i = 1; i < MM; i++) {
        float lx = sx[last], ly = sy[last], lz = sz[last];
        float bv = -1.0f;
        unsigned bj = 0;
#pragma unroll
        for (int s = 0; s < 4; s++) {
            float dx = x[s] - lx, dy = y[s] - ly, dz = z[s] - lz;
            // strict order, no fma: (dx*dx + dy*dy) + dz*dz
            float d = __fadd_rn(__fadd_rn(__fmul_rn(dx, dx), __fmul_rn(dy, dy)),
                                __fmul_rn(dz, dz));
            float nd = fminf(dist[s], d);
            dist[s] = nd;
            if (nd > bv) { bv = nd; bj = (unsigned)(tid + s * 1024); }  // ascending j: strict > keeps min idx
        }
        // warp argmax with first-index tie-break (dist >= 0 so float bits are order-preserving)
        unsigned vb = __float_as_uint(bv);
        unsigned wm = __reduce_max_sync(0xffffffffu, vb);
        unsigned cj = (vb == wm) ? bj : 0xffffffffu;
        unsigned wj = __reduce_min_sync(0xffffffffu, cj);
        if (lane == 0) swp[wid] = make_uint2(wm, wj);
        __syncthreads();
        if (wid == 0) {
            uint2 e = swp[lane];
            unsigned gm  = __reduce_max_sync(0xffffffffu, e.x);
            unsigned cj2 = (e.x == gm) ? e.y : 0xffffffffu;
            unsigned gj  = __reduce_min_sync(0xffffffffu, cj2);
            if (lane == 0) {
                s_last = (int)gj;
                g_fps[b * MM + i] = (int)gj;
            }
        }
        __syncthreads();
        last = s_last;
    }
}

// ============================================================
// MLP: h = feat @ W + b, plus deterministic per-block BN partials.
// Block = 128 threads (one per out col), 32 rows per block.
// ============================================================
__global__ void mlp_kernel(const float* __restrict__ feat,
                           const float* __restrict__ W,
                           const float* __restrict__ bias)
{
    __shared__ __align__(16) float sW[FIN * FOUT];   // 32 KB
    __shared__ __align__(16) float sF[32 * FIN];     // 8 KB

    const int tid  = threadIdx.x;
    const int row0 = blockIdx.x * 32;

    for (int l = tid; l < FIN * FOUT; l += 128) sW[l] = W[l];
    for (int l = tid; l < 32 * FIN;   l += 128) sF[l] = feat[(size_t)row0 * FIN + l];
    __syncthreads();

    const int col = tid;
    const float bc = bias[col];
    float s1 = 0.f, s2 = 0.f;
    const float4* sF4 = reinterpret_cast<const float4*>(sF);

    for (int r = 0; r < 32; r += 2) {
        float a0 = bc, a1 = bc;
#pragma unroll
        for (int d4 = 0; d4 < FIN / 4; d4++) {
            float4 f0 = sF4[r * (FIN / 4) + d4];
            float4 f1 = sF4[(r + 1) * (FIN / 4) + d4];
            float w0 = sW[(d4 * 4 + 0) * FOUT + col];
            float w1 = sW[(d4 * 4 + 1) * FOUT + col];
            float w2 = sW[(d4 * 4 + 2) * FOUT + col];
            float w3 = sW[(d4 * 4 + 3) * FOUT + col];
            a0 += f0.x * w0; a0 += f0.y * w1; a0 += f0.z * w2; a0 += f0.w * w3;
            a1 += f1.x * w0; a1 += f1.y * w1; a1 += f1.z * w2; a1 += f1.w * w3;
        }
        g_h[(size_t)(row0 + r)     * FOUT + col] = a0;
        g_h[(size_t)(row0 + r + 1) * FOUT + col] = a1;
        s1 += a0 + a1;
        s2 += a0 * a0 + a1 * a1;
    }
    g_psum[blockIdx.x * FOUT + col] = s1;
    g_psq [blockIdx.x * FOUT + col] = s2;
}

// Deterministic BN stat reduction: one block per column, fixed-order tree.
__global__ void bn_reduce_kernel()
{
    __shared__ float r1[256], r2[256];
    const int col = blockIdx.x;
    const int tid = threadIdx.x;
    float s1 = 0.f, s2 = 0.f;
    for (int i = tid; i < (NN / 32); i += 256) {
        s1 += g_psum[i * FOUT + col];
        s2 += g_psq [i * FOUT + col];
    }
    r1[tid] = s1; r2[tid] = s2;
    __syncthreads();
    for (int off = 128; off > 0; off >>= 1) {
        if (tid < off) { r1[tid] += r1[tid + off]; r2[tid] += r2[tid + off]; }
        __syncthreads();
    }
    if (tid == 0) {
        float mean = r1[0] / (float)NN;
        float var  = r2[0] / (float)NN - mean * mean;
        if (var < 0.f) var = 0.f;
        g_mean[col] = mean;
        g_var [col] = var;
    }
}

// Per-point feature-space squared norms (for KNN d2 = qq - 2*dot + xx).
__global__ void xx_kernel(const float* __restrict__ feat)
{
    int row = blockIdx.x * blockDim.x + threadIdx.x;
    if (row >= NN) return;
    const float4* fr = reinterpret_cast<const float4*>(feat + (size_t)row * FIN);
    float a0 = 0.f, a1 = 0.f, a2 = 0.f, a3 = 0.f;
#pragma unroll
    for (int d = 0; d < FIN / 4; d++) {
        float4 v = fr[d];
        a0 += v.x * v.x; a1 += v.y * v.y; a2 += v.z * v.z; a3 += v.w * v.w;
    }
    g_xx[row] = (a0 + a1) + (a2 + a3);
}

// ============================================================
// KNN in feature space: block = 128 queries (one per thread),
// q (64 f32) in registers, candidate tiles of 32 rows in shared.
// Top-16 smallest d2 maintained in registers (unrolled predicated
// insert). Ties: first index wins (matches lax.top_k set semantics).
// ============================================================
__global__ void knn_kernel(const float* __restrict__ feat)
{
    __shared__ __align__(16) float sX[32 * FIN];   // 8 KB tile
    __shared__ float sxx[32];

    const int tid = threadIdx.x;
    const int b   = blockIdx.x >> 3;
    const int m   = ((blockIdx.x & 7) << 7) + tid;

    const int qi = g_fps[b * MM + m];
    const float4* qrow = reinterpret_cast<const float4*>(feat + ((size_t)b * PP + qi) * FIN);
    float4 q4[FIN / 4];
#pragma unroll
    for (int d = 0; d < FIN / 4; d++) q4[d] = qrow[d];
    const float qq = g_xx[(size_t)b * PP + qi];

    float topv[KK];
    int   topi[KK];
#pragma unroll
    for (int s = 0; s < KK; s++) { topv[s] = INFINITY; topi[s] = 0x7fffffff; }
    float worst = INFINITY;

    const float4* fb = reinterpret_cast<const float4*>(feat + (size_t)b * PP * FIN);
    float4* sX4 = reinterpret_cast<float4*>(sX);

    for (int p0 = 0; p0 < PP; p0 += 32) {
        __syncthreads();
#pragma unroll
        for (int i = 0; i < 4; i++) {
            int l = tid + i * 128;                  // 512 float4 = 32 rows x 16
            sX4[l] = fb[(size_t)p0 * (FIN / 4) + l];
        }
        if (tid < 32) sxx[tid] = g_xx[(size_t)b * PP + p0 + tid];
        __syncthreads();

#pragma unroll 2
        for (int c = 0; c < 32; c++) {
            const float4* xr = reinterpret_cast<const float4*>(sX + c * FIN);
            float a0 = 0.f, a1 = 0.f, a2 = 0.f, a3 = 0.f;
#pragma unroll
            for (int d = 0; d < FIN / 4; d++) {
                float4 xv = xr[d];
                a0 += q4[d].x * xv.x; a1 += q4[d].y * xv.y;
                a2 += q4[d].z * xv.z; a3 += q4[d].w * xv.w;
            }
            float dot = (a0 + a1) + (a2 + a3);
            float d2  = (qq - 2.0f * dot) + sxx[c];
            if (d2 < worst) {
                int cand = p0 + c;
                // find eviction slot: max val; tie -> evict larger stored idx
                float mv = topv[0]; int mi = topi[0]; int msl = 0;
#pragma unroll
                for (int s = 1; s < KK; s++) {
                    bool better = (topv[s] > mv) || (topv[s] == mv && topi[s] > mi);
                    if (better) { mv = topv[s]; mi = topi[s]; msl = s; }
                }
#pragma unroll
                for (int s = 0; s < KK; s++) {
                    if (s == msl) { topv[s] = d2; topi[s] = cand; }
                }
                worst = topv[0];
#pragma unroll
                for (int s = 1; s < KK; s++) worst = fmaxf(worst, topv[s]);
            }
        }
    }

    int qidx = b * MM + m;
#pragma unroll
    for (int s = 0; s < KK; s++) g_knn[qidx * KK + s] = topi[s];
}

// ============================================================
// Gather + fused BN + ReLU + max-pool over K neighbors.
// Also writes new_position and new_batch.
// ============================================================
__global__ void gather_kernel(const float* __restrict__ pos,
                              const float* __restrict__ gamma,
                              const float* __restrict__ beta,
                              float* __restrict__ out,
                              int out_size)
{
    __shared__ int sidx[KK];
    __shared__ int sfps;
    const int q   = blockIdx.x;
    const int b   = q >> 10;
    const int tid = threadIdx.x;

    if (tid < KK) sidx[tid] = g_knn[q * KK + tid];
    if (tid == KK) sfps = g_fps[q];
    __syncthreads();

    const int col = tid;
    float mean = g_mean[col];
    float rstd = rsqrtf(g_var[col] + BN_EPS);
    float ga = gamma[col], be = beta[col];
    const float* hb = g_h + (size_t)b * PP * FOUT;

    float mx = -INFINITY;
#pragma unroll
    for (int k = 0; k < KK; k++) {
        float v = hb[(size_t)sidx[k] * FOUT + col];
        v = (v - mean) * rstd * ga + be;
        v = fmaxf(v, 0.f);
        mx = fmaxf(mx, v);
    }
    out[(size_t)q * FOUT + col] = mx;

    if (out_size >= TOTAL_OUT) {
        if (tid < 3) out[OFF_P + q * 3 + tid] = pos[((size_t)b * PP + sfps) * 3 + tid];
        if (tid == 3) out[OFF_B + q] = (float)b;
    }
}

// ============================================================
extern "C" void kernel_launch(void* const* d_in, const int* in_sizes, int n_in,
                              void* d_out, int out_size)
{
    const float* pos   = (const float*)d_in[0];
    const float* feat  = (const float*)d_in[1];
    // d_in[2] = batch_indices (unused: clouds are sorted & equal-sized)
    const float* W     = (const float*)d_in[3];
    const float* bias  = (const float*)d_in[4];
    const float* gamma = (const float*)d_in[5];
    const float* beta  = (const float*)d_in[6];
    float* out = (float*)d_out;

    const int fps_smem = 3 * PP * sizeof(float) + 32 * sizeof(uint2);
    cudaFuncSetAttribute(fps_kernel, cudaFuncAttributeMaxDynamicSharedMemorySize, fps_smem);

    // independent of FPS:
    mlp_kernel<<<NN / 32, 128>>>(feat, W, bias);
    bn_reduce_kernel<<<FOUT, 256>>>();
    xx_kernel<<<(NN + 127) / 128, 128>>>(feat);

    // FPS -> KNN -> gather
    fps_kernel<<<BB, 1024, fps_smem>>>(pos);
    knn_kernel<<<BB * (MM / 128), 128>>>(feat);
    gather_kernel<<<BB * MM, 128>>>(pos, gamma, beta, out, out_size);
}

// round 3
// speedup vs baseline: 1.5908x; 1.5908x over previous
#include <cuda_runtime.h>
#include <cuda_bf16.h>
#include <math.h>

// Problem constants
#define BB   16
#define PP   4096
#define MM   1024
#define KK   16
#define FIN  64
#define FOUT 128
#define NN   (BB * PP)          // 65536
#define BN_EPS 1e-5f

#define OFF_P  (BB * MM * FOUT)            // 2097152
#define OFF_B  (OFF_P + BB * MM * 3)       // 2146304
#define TOTAL_OUT (OFF_B + BB * MM)        // 2162688

// f32x2 packed ops (sm_103a). fma.rn.f32x2 / add.rn.f32x2 / mul.rn.f32x2 are
// two independent rn-rounded fp32 ops -> bitwise identical to scalar code.
#define PACK2(o, lo, hi)  asm("mov.b64 %0, {%1, %2};" : "=l"(o) : "f"(lo), "f"(hi))
#define UNPACK2(lo, hi, i) asm("mov.b64 {%0, %1}, %2;" : "=f"(lo), "=f"(hi) : "l"(i))
#define FMA2(acc, a, b)   asm("fma.rn.f32x2 %0, %1, %2, %0;" : "+l"(acc) : "l"(a), "l"(b))
#define ADD2(o, a, b)     asm("add.rn.f32x2 %0, %1, %2;" : "=l"(o) : "l"(a), "l"(b))
#define MUL2(o, a, b)     asm("mul.rn.f32x2 %0, %1, %2;" : "=l"(o) : "l"(a), "l"(b))

typedef unsigned long long ull;

// -------- scratch (static device globals; no allocation allowed) --------
__device__ int   g_fps[BB * MM];
__device__ int   g_knn[BB * MM * KK];
__device__ float g_h[(size_t)NN * FOUT];        // 33.5 MB pre-BN activations
__device__ float g_psum[(NN / 32) * FOUT];      // 2048 x 128 partial sums
__device__ float g_psq [(NN / 32) * FOUT];
__device__ float g_mean[FOUT];
__device__ float g_var [FOUT];
__device__ float g_xx[NN];                      // per-point sum(x*x) in feature space

// ============================================================
// Fused kernel: blocks 0..15 run FPS (one cloud each, 1024 thr),
// blocks 16..271 run the MLP (+xx) on 256 rows each (1024 thr).
// They are independent and run concurrently.
// ============================================================
__global__ void __launch_bounds__(1024) fused_fps_mlp_kernel(
    const float* __restrict__ pos,
    const float* __restrict__ feat,
    const float* __restrict__ W,
    const float* __restrict__ bias)
{
    extern __shared__ float fsm[];
    const int tid = threadIdx.x;

    if (blockIdx.x < BB) {
        // ---------------- FPS path ----------------
        float* sx = fsm;
        float* sy = fsm + PP;
        float* sz = fsm + 2 * PP;
        uint2* swp = (uint2*)(fsm + 3 * PP);   // double-buffered: 2 x 32

        const int b    = blockIdx.x;
        const int lane = tid & 31;
        const int wid  = tid >> 5;

        const float* pb = pos + (size_t)b * PP * 3;
        for (int j = tid; j < PP; j += 1024) {
            sx[j] = pb[3 * j + 0];
            sy[j] = pb[3 * j + 1];
            sz[j] = pb[3 * j + 2];
        }
        __syncthreads();

        // 4 points per thread as 2 packed pairs: slots (tid, tid+1024), (tid+2048, tid+3072)
        float x0 = sx[tid],        x1 = sx[tid + 1024], x2 = sx[tid + 2048], x3 = sx[tid + 3072];
        float y0 = sy[tid],        y1 = sy[tid + 1024], y2 = sy[tid + 2048], y3 = sy[tid + 3072];
        float z0 = sz[tid],        z1 = sz[tid + 1024], z2 = sz[tid + 2048], z3 = sz[tid + 3072];
        ull X01, X23, Y01, Y23, Z01, Z23;
        PACK2(X01, x0, x1); PACK2(X23, x2, x3);
        PACK2(Y01, y0, y1); PACK2(Y23, y2, y3);
        PACK2(Z01, z0, z1); PACK2(Z23, z2, z3);
        float dist0 = INFINITY, dist1 = INFINITY, dist2 = INFINITY, dist3 = INFINITY;

        if (tid == 0) g_fps[b * MM] = 0;

        int last = 0;
        for (int i = 1; i < MM; i++) {
            float lx = sx[last], ly = sy[last], lz = sz[last];
            float nlx = -lx, nly = -ly, nlz = -lz;
            ull NLX, NLY, NLZ;
            PACK2(NLX, nlx, nlx); PACK2(NLY, nly, nly); PACK2(NLZ, nlz, nlz);

            // pair 01:  d = ((dx*dx + dy*dy) + dz*dz), no fma -> bitwise == scalar rn
            ull dx, dy, dz, mx, my, mz, t, d01, d23;
            ADD2(dx, X01, NLX); ADD2(dy, Y01, NLY); ADD2(dz, Z01, NLZ);
            MUL2(mx, dx, dx); MUL2(my, dy, dy); MUL2(mz, dz, dz);
            ADD2(t, mx, my); ADD2(d01, t, mz);
            // pair 23
            ADD2(dx, X23, NLX); ADD2(dy, Y23, NLY); ADD2(dz, Z23, NLZ);
            MUL2(mx, dx, dx); MUL2(my, dy, dy); MUL2(mz, dz, dz);
            ADD2(t, mx, my); ADD2(d23, t, mz);

            float d0, d1, d2f, d3f;
            UNPACK2(d0, d1, d01); UNPACK2(d2f, d3f, d23);

            dist0 = fminf(dist0, d0);
            dist1 = fminf(dist1, d1);
            dist2 = fminf(dist2, d2f);
            dist3 = fminf(dist3, d3f);

            // per-thread argmax (ascending slot index, strict > keeps min index)
            float bv = -1.0f; unsigned bj = 0;
            if (dist0 > bv) { bv = dist0; bj = (unsigned)tid; }
            if (dist1 > bv) { bv = dist1; bj = (unsigned)(tid + 1024); }
            if (dist2 > bv) { bv = dist2; bj = (unsigned)(tid + 2048); }
            if (dist3 > bv) { bv = dist3; bj = (unsigned)(tid + 3072); }

            // warp argmax with first-index tie-break (dist >= 0 -> bits order-preserving)
            unsigned vb = __float_as_uint(bv);
            unsigned wm = __reduce_max_sync(0xffffffffu, vb);
            unsigned cj = (vb == wm) ? bj : 0xffffffffu;
            unsigned wj = __reduce_min_sync(0xffffffffu, cj);

            uint2* buf = swp + ((i & 1) << 5);
            if (lane == 0) buf[wid] = make_uint2(wm, wj);
            __syncthreads();
            // all warps redundantly reduce the 32 warp results (no 2nd barrier:
            // next iter writes the OTHER buffer; the barrier of iter i+1 protects reuse)
            uint2 e = buf[lane];
            unsigned gm  = __reduce_max_sync(0xffffffffu, e.x);
            unsigned cj2 = (e.x == gm) ? e.y : 0xffffffffu;
            unsigned gj  = __reduce_min_sync(0xffffffffu, cj2);
            last = (int)gj;
            if (tid == 0) g_fps[b * MM + i] = last;
        }
    } else {
        // ---------------- MLP (+xx) path: 256 rows per block ----------------
        float* sW = fsm;               // 64*128 = 8192 floats (32 KB)
        float* sF = fsm + FIN * FOUT;  // 256*64 = 16384 floats (64 KB)

        const int row0 = (blockIdx.x - BB) * 256;

        for (int l = tid; l < FIN * FOUT; l += 1024) sW[l] = W[l];
        float4* sF4 = (float4*)sF;
        const float4* feat4 = (const float4*)(feat + (size_t)row0 * FIN);
        for (int l = tid; l < 256 * (FIN / 4); l += 1024) sF4[l] = feat4[l];
        __syncthreads();

        // xx for these 256 rows (same 4-accumulator arithmetic as R1)
        if (tid < 256) {
            float a0 = 0.f, a1 = 0.f, a2 = 0.f, a3 = 0.f;
#pragma unroll
            for (int d = 0; d < FIN / 4; d++) {
                float4 v = sF4[tid * (FIN / 4) + d];
                a0 += v.x * v.x; a1 += v.y * v.y; a2 += v.z * v.z; a3 += v.w * v.w;
            }
            g_xx[row0 + tid] = (a0 + a1) + (a2 + a3);
        }

        const int col = tid & 127;
        const int grp = tid >> 7;          // 0..7, 32 rows each
        const int rbase = grp * 32;
        const float bc = bias[col];
        float s1 = 0.f, s2 = 0.f;

        for (int r = rbase; r < rbase + 32; r += 2) {
            float a0 = bc, a1 = bc;
#pragma unroll
            for (int d4 = 0; d4 < FIN / 4; d4++) {
                float4 f0 = sF4[r * (FIN / 4) + d4];
                float4 f1 = sF4[(r + 1) * (FIN / 4) + d4];
                float w0 = sW[(d4 * 4 + 0) * FOUT + col];
                float w1 = sW[(d4 * 4 + 1) * FOUT + col];
                float w2 = sW[(d4 * 4 + 2) * FOUT + col];
                float w3 = sW[(d4 * 4 + 3) * FOUT + col];
                a0 += f0.x * w0; a0 += f0.y * w1; a0 += f0.z * w2; a0 += f0.w * w3;
                a1 += f1.x * w0; a1 += f1.y * w1; a1 += f1.z * w2; a1 += f1.w * w3;
            }
            g_h[(size_t)(row0 + r)     * FOUT + col] = a0;
            g_h[(size_t)(row0 + r + 1) * FOUT + col] = a1;
            s1 += a0 + a1;
            s2 += a0 * a0 + a1 * a1;
        }
        const int prow = row0 / 32 + grp;   // 0..2047
        g_psum[prow * FOUT + col] = s1;
        g_psq [prow * FOUT + col] = s2;
    }
}

// Deterministic BN stat reduction: one block per column, fixed-order tree.
__global__ void bn_reduce_kernel()
{
    __shared__ float r1[256], r2[256];
    const int col = blockIdx.x;
    const int tid = threadIdx.x;
    float s1 = 0.f, s2 = 0.f;
    for (int i = tid; i < (NN / 32); i += 256) {
        s1 += g_psum[i * FOUT + col];
        s2 += g_psq [i * FOUT + col];
    }
    r1[tid] = s1; r2[tid] = s2;
    __syncthreads();
    for (int off = 128; off > 0; off >>= 1) {
        if (tid < off) { r1[tid] += r1[tid + off]; r2[tid] += r2[tid + off]; }
        __syncthreads();
    }
    if (tid == 0) {
        float mean = r1[0] / (float)NN;
        float var  = r2[0] / (float)NN - mean * mean;
        if (var < 0.f) var = 0.f;
        g_mean[col] = mean;
        g_var [col] = var;
    }
}

// ============================================================
// KNN: 128 blocks x 512 threads. Block covers 128 queries of one
// cloud chunk; 4 candidate-subsets of 1024 each (sub = tid>>7).
// Dot products via fma.rn.f32x2 (bitwise == 4-accumulator FFMA chains).
// Per-sub exact top-16, then exact (d2,idx)-keyed merge in shared.
// ============================================================
__global__ void __launch_bounds__(512) knn_kernel(const float* __restrict__ feat)
{
    extern __shared__ char ksm[];
    float* sTile = (float*)ksm;                          // 4*32*64 f32 = 32 KB (loop phase)
    ull*   mbuf  = (ull*)ksm;                            // 64*128*8B = 64 KB (merge phase)
    float* sxx   = (float*)(ksm + 65536);                // 4*32 f32

    const int tid = threadIdx.x;
    const int sub = tid >> 7;          // 0..3
    const int q   = tid & 127;
    const int b     = blockIdx.x >> 3;
    const int chunk = blockIdx.x & 7;
    const int m = chunk * 128 + q;

    const int qi = g_fps[b * MM + m];
    const float4* qrow = (const float4*)(feat + ((size_t)b * PP + qi) * FIN);
    ull qp[32];
#pragma unroll
    for (int d = 0; d < FIN / 4; d++) {
        float4 f = qrow[d];
        PACK2(qp[2 * d],     f.x, f.y);
        PACK2(qp[2 * d + 1], f.z, f.w);
    }
    const float qq = g_xx[(size_t)b * PP + qi];

    float topv[KK];
    int   topi[KK];
#pragma unroll
    for (int s = 0; s < KK; s++) { topv[s] = INFINITY; topi[s] = 0x7fffffff; }
    float worst = INFINITY;

    const float4* fb4 = (const float4*)(feat + (size_t)b * PP * FIN);
    float4* sT4 = (float4*)sTile;

    for (int p0 = 0; p0 < 1024; p0 += 32) {
        __syncthreads();
        // cooperative tile load: pass i loads sub i's 32 rows
#pragma unroll
        for (int i = 0; i < 4; i++) {
            int row = tid >> 4;          // 0..31
            int c4  = tid & 15;
            int grow = i * 1024 + p0 + row;
            sT4[i * 512 + tid] = fb4[(size_t)grow * (FIN / 4) + c4];
            (void)c4;
        }
        if (tid < 128) {
            int sx_sub = tid >> 5, r = tid & 31;
            sxx[tid] = g_xx[(size_t)b * PP + sx_sub * 1024 + p0 + r];
        }
        __syncthreads();

#pragma unroll 2
        for (int c = 0; c < 32; c++) {
            const ulonglong2* xr = (const ulonglong2*)(sTile + (size_t)(sub * 32 + c) * FIN);
            ull a01 = 0ull, a23 = 0ull;
#pragma unroll
            for (int d = 0; d < FIN / 4; d++) {
                ulonglong2 xv = xr[d];
                FMA2(a01, qp[2 * d],     xv.x);
                FMA2(a23, qp[2 * d + 1], xv.y);
            }
            float a0, a1, a2, a3;
            UNPACK2(a0, a1, a01);
            UNPACK2(a2, a3, a23);
            float dot = (a0 + a1) + (a2 + a3);
            float d2  = (qq - 2.0f * dot) + sxx[sub * 32 + c];
            if (d2 < worst) {
                int cand = sub * 1024 + p0 + c;
                float mv = topv[0]; int mi = topi[0]; int msl = 0;
#pragma unroll
                for (int s = 1; s < KK; s++) {
                    bool better = (topv[s] > mv) || (topv[s] == mv && topi[s] > mi);
                    if (better) { mv = topv[s]; mi = topi[s]; msl = s; }
                }
#pragma unroll
                for (int s = 0; s < KK; s++) {
                    if (s == msl) { topv[s] = d2; topi[s] = cand; }
                }
                worst = topv[0];
#pragma unroll
                for (int s = 1; s < KK; s++) worst = fmaxf(worst, topv[s]);
            }
        }
    }

    // ---- exact merge: key = (monotone(d2) << 32) | idx ----
    __syncthreads();   // tile reads done; reuse smem as mbuf
#pragma unroll
    for (int s = 0; s < KK; s++) {
        unsigned v = __float_as_uint(topv[s]);
        unsigned u = (v & 0x80000000u) ? ~v : (v | 0x80000000u);
        mbuf[(size_t)(sub * KK + s) * 128 + q] = ((ull)u << 32) | (unsigned)topi[s];
    }
    __syncthreads();

    if (sub == 0) {
        int base = (b * MM + m) * KK;
#pragma unroll 1
        for (int k = 0; k < KK; k++) {
            ull best = 0xffffffffffffffffull; int jb = 0;
            for (int j = 0; j < 64; j++) {
                ull e = mbuf[(size_t)j * 128 + q];
                if (e < best) { best = e; jb = j; }
            }
            mbuf[(size_t)jb * 128 + q] = 0xffffffffffffffffull;
            g_knn[base + k] = (int)(unsigned)(best & 0xffffffffu);
        }
    }
}

// ============================================================
// Gather + fused BN + ReLU + max-pool over K neighbors.
// Also writes new_position and new_batch.
// ============================================================
__global__ void gather_kernel(const float* __restrict__ pos,
                              const float* __restrict__ gamma,
                              const float* __restrict__ beta,
                              float* __restrict__ out,
                              int out_size)
{
    __shared__ int sidx[KK];
    __shared__ int sfps;
    const int q   = blockIdx.x;
    const int b   = q >> 10;
    const int tid = threadIdx.x;

    if (tid < KK) sidx[tid] = g_knn[q * KK + tid];
    if (tid == KK) sfps = g_fps[q];
    __syncthreads();

    const int col = tid;
    float mean = g_mean[col];
    float rstd = rsqrtf(g_var[col] + BN_EPS);
    float ga = gamma[col], be = beta[col];
    const float* hb = g_h + (size_t)b * PP * FOUT;

    float mx = -INFINITY;
#pragma unroll
    for (int k = 0; k < KK; k++) {
        float v = hb[(size_t)sidx[k] * FOUT + col];
        v = (v - mean) * rstd * ga + be;
        v = fmaxf(v, 0.f);
        mx = fmaxf(mx, v);
    }
    out[(size_t)q * FOUT + col] = mx;

    if (out_size >= TOTAL_OUT) {
        if (tid < 3) out[OFF_P + q * 3 + tid] = pos[((size_t)b * PP + sfps) * 3 + tid];
        if (tid == 3) out[OFF_B + q] = (float)b;
    }
}

// ============================================================
extern "C" void kernel_launch(void* const* d_in, const int* in_sizes, int n_in,
                              void* d_out, int out_size)
{
    const float* pos   = (const float*)d_in[0];
    const float* feat  = (const float*)d_in[1];
    // d_in[2] = batch_indices (unused: clouds are sorted & equal-sized)
    const float* W     = (const float*)d_in[3];
    const float* bias  = (const float*)d_in[4];
    const float* gamma = (const float*)d_in[5];
    const float* beta  = (const float*)d_in[6];
    float* out = (float*)d_out;

    // fused kernel smem: max(FPS: 48KB + 512B, MLP: 32KB + 64KB) = 96 KB
    const int fused_smem = (FIN * FOUT + 256 * FIN) * sizeof(float);   // 98304
    cudaFuncSetAttribute(fused_fps_mlp_kernel, cudaFuncAttributeMaxDynamicSharedMemorySize, fused_smem);
    const int knn_smem = 65536 + 4 * 32 * sizeof(float);               // 66048
    cudaFuncSetAttribute(knn_kernel, cudaFuncAttributeMaxDynamicSharedMemorySize, knn_smem);

    // FPS (16 blocks) runs concurrently with MLP+xx (256 blocks).
    fused_fps_mlp_kernel<<<BB + 256, 1024, fused_smem>>>(pos, feat, W, bias);
    knn_kernel<<<BB * (MM / 128), 512, knn_smem>>>(feat);
    bn_reduce_kernel<<<FOUT, 256>>>();
    gather_kernel<<<BB * MM, 128>>>(pos, gamma, beta, out, out_size);
}